// round 10
// baseline (speedup 1.0000x reference)
#include <cuda_runtime.h>
#include <math.h>

#define T_LEN 32
#define KP    2048
#define CPB   7                        // columns per CTA (1 warp per column)
#define BLOCK (CPB * 32)               // 224 threads, 7 warps
#define GRID  293                      // ceil(2048/7) -> ~2 CTAs/SM, balanced

// sp = sqrt(1/32); 0.5/sp^2 = 16 exactly
#define LOG_SP     (-1.7328679513998633f)
#define HALF_L2PI  (0.9189385332046727f)
#define LOG_K      (7.6246189861593985f)
#define C2EXP      (-23.083120654223414f)   // -16 * log2(e)
#define L2E        (1.4426950408889634f)
#define F_INF      (__int_as_float(0x7f800000))

__device__ float g_zs[T_LEN * KP];
__device__ float g_A [T_LEN * KP];
__device__ float g_rb[T_LEN][KP];

__device__ __forceinline__ float ex2(float t) {
    float r; asm("ex2.approx.ftz.f32 %0,%1;" : "=f"(r) : "f"(t)); return r;
}

// Setup: zs = mu + sigma*eps; A = -log(sp)-0.5log2pi-log_q; r0
__global__ void __launch_bounds__(256) setup_kernel(const float* __restrict__ means,
                                                    const float* __restrict__ log_stds,
                                                    const float* __restrict__ eps) {
    int idx = blockIdx.x * 256 + threadIdx.x;      // grid covers T_LEN*KP exactly
    int t = idx >> 11;
    int k = idx & (KP - 1);
    float mu = means[t];
    float sg = expf(log_stds[t]);
    float z  = fmaf(sg, eps[idx], mu);
    float zq = (z - mu) / sg;
    float lq = fmaf(-0.5f * zq, zq, -logf(sg)) - HALF_L2PI;
    g_zs[idx] = z;
    g_A[idx]  = -LOG_SP - HALF_L2PI - lq;
    if (t == 0) {
        float zz = z * 5.656854249492380f;         // z / sp
        g_rb[0][k] = fmaf(-0.5f * zz, zz, -LOG_SP) - HALF_L2PI - lq;
    }
}

// One scan step with PDL: z-prologue overlaps predecessor; sync only before r.
__global__ void __launch_bounds__(BLOCK, 2) step_kernel(int t) {
    __shared__ __align__(16) float2 s[KP];    // (-z_{t-1,j}, (r_j - x)*log2e)
    __shared__ float red[CPB];

    const int tid  = threadIdx.x;
    const int wid  = tid >> 5;                 // column-in-block 0..6
    const int lane = tid & 31;
    const int k    = blockIdx.x * CPB + wid;

    cudaTriggerProgrammaticLaunchCompletion();         // successor may launch now
    if (t == 1) cudaGridDependencySynchronize();       // setup may still be running

    // ---- independent prologue (setup data only) ----
    const float* __restrict__ zrow = g_zs + (t - 1) * KP;
    for (int j = tid; j < KP; j += BLOCK)
        s[j].x = -zrow[j];
    float zk = 0.0f, ak = 0.0f;
    if (k < KP) { zk = g_zs[t * KP + k]; ak = g_A[t * KP + k]; }

    cudaGridDependencySynchronize();                   // wait for r_{t-1}

    // ---- load r, block max, build lu ----
    const float* __restrict__ rin = g_rb[t - 1];
    float rv[10];
    float lm = -F_INF;
    int nr = 0;
    for (int j = tid; j < KP; j += BLOCK, nr++) {
        float r = rin[j];
        rv[nr] = r;
        lm = fmaxf(lm, r);
    }
    #pragma unroll
    for (int m = 16; m; m >>= 1)
        lm = fmaxf(lm, __shfl_xor_sync(0xffffffffu, lm, m));
    if (lane == 0) red[wid] = lm;
    __syncthreads();
    float x = red[0];
    #pragma unroll
    for (int w = 1; w < CPB; w++) x = fmaxf(x, red[w]);
    {
        int i = 0;
        for (int j = tid; j < KP; j += BLOCK, i++)
            s[j].y = (rv[i] - x) * L2E;
    }
    __syncthreads();

    // ---- mainloop: S = sum_j 2^(C2*d^2 + (r_j-x)*log2e) ----
    if (k < KP) {
        float S0 = 0.0f, S1 = 0.0f;
        #pragma unroll 8
        for (int i = 0; i < KP / 64; i++) {            // 32 iters, 2 pairs each
            int f = i * 32 + lane;                     // float4 chunk index
            float4 v = *reinterpret_cast<const float4*>(&s[2 * f]);
            float d0 = zk + v.x;
            float d1 = zk + v.z;
            float t0 = fmaf(d0 * C2EXP, d0, v.y);
            float t1 = fmaf(d1 * C2EXP, d1, v.w);
            S0 += ex2(t0);                             // MUFU, flushes tiny to 0
            S1 += ex2(t1);
        }
        float S = S0 + S1;
        #pragma unroll
        for (int m = 16; m; m >>= 1)
            S += __shfl_xor_sync(0xffffffffu, S, m);
        if (lane == 0)
            g_rb[t][k] = x + ak + logf(fmaxf(S, 1e-37f)) - LOG_K;
    }
}

// Final: out = x + y + log(sum_j exp(r_j - x)*exp(L_j - y)) - logK
__global__ void __launch_bounds__(256) final_kernel(float* __restrict__ out) {
    __shared__ float sr[KP];
    __shared__ float sL[KP];
    __shared__ float red[16];
    const int tid  = threadIdx.x;
    const int wid  = tid >> 5;
    const int lane = tid & 31;

    cudaGridDependencySynchronize();

    const float* __restrict__ zrow = g_zs + (T_LEN - 1) * KP;
    const float* __restrict__ rin  = g_rb[T_LEN - 1];
    float lr = -F_INF, lL = -F_INF;
    #pragma unroll
    for (int i = 0; i < KP / 256; i++) {
        int j = tid + i * 256;
        float r  = rin[j];
        float dd = 0.5f - zrow[j];
        float Lv = fmaf(-0.5f * dd, dd, -HALF_L2PI);
        sr[j] = r; sL[j] = Lv;
        lr = fmaxf(lr, r);
        lL = fmaxf(lL, Lv);
    }
    #pragma unroll
    for (int m = 16; m; m >>= 1) {
        lr = fmaxf(lr, __shfl_xor_sync(0xffffffffu, lr, m));
        lL = fmaxf(lL, __shfl_xor_sync(0xffffffffu, lL, m));
    }
    if (lane == 0) { red[wid] = lr; red[8 + wid] = lL; }
    __syncthreads();
    float x = red[0], y = red[8];
    #pragma unroll
    for (int w = 1; w < 8; w++) {
        x = fmaxf(x, red[w]);
        y = fmaxf(y, red[8 + w]);
    }

    float S = 0.0f;
    #pragma unroll
    for (int i = 0; i < KP / 256; i++) {
        int j = tid + i * 256;
        S += ex2(((sr[j] - x) + (sL[j] - y)) * L2E);
    }
    #pragma unroll
    for (int m = 16; m; m >>= 1)
        S += __shfl_xor_sync(0xffffffffu, S, m);
    if (lane == 0) red[wid] = S;
    __syncthreads();
    if (tid == 0) {
        float tot = 0.0f;
        #pragma unroll
        for (int w = 0; w < 8; w++) tot += red[w];
        out[0] = x + y + logf(tot) - LOG_K;
    }
}

extern "C" void kernel_launch(void* const* d_in, const int* in_sizes, int n_in,
                              void* d_out, int out_size) {
    const float* means    = (const float*)d_in[0];
    const float* log_stds = (const float*)d_in[1];
    const float* eps      = (const float*)d_in[2];
    float* out = (float*)d_out;

    setup_kernel<<<(T_LEN * KP) / 256, 256>>>(means, log_stds, eps);

    cudaLaunchAttribute attr[1];
    attr[0].id = cudaLaunchAttributeProgrammaticStreamSerialization;
    attr[0].val.programmaticStreamSerializationAllowed = 1;

    cudaLaunchConfig_t cfg = {};
    cfg.gridDim  = dim3(GRID, 1, 1);
    cfg.blockDim = dim3(BLOCK, 1, 1);
    cfg.dynamicSmemBytes = 0;
    cfg.stream = 0;
    cfg.attrs = attr;
    cfg.numAttrs = 1;

    for (int t = 1; t < T_LEN; t++)
        cudaLaunchKernelEx(&cfg, step_kernel, t);

    cudaLaunchConfig_t cfgf = cfg;
    cfgf.gridDim  = dim3(1, 1, 1);
    cfgf.blockDim = dim3(256, 1, 1);
    cudaLaunchKernelEx(&cfgf, final_kernel, out);
}

// round 11
// speedup vs baseline: 1.2647x; 1.2647x over previous
#include <cuda_runtime.h>
#include <math.h>

#define T_LEN 32
#define KP    2048
#define CPB   16                       // columns per CTA
#define GPC   16                       // threads per column
#define BLOCK 256
#define GRID  128                      // 128*16 = 2048 columns, single wave

// sp = sqrt(1/32); 0.5/sp^2 = 16 exactly
#define LOG_SP     (-1.7328679513998633f)
#define HALF_L2PI  (0.9189385332046727f)
#define LOG_K      (7.6246189861593985f)
#define C2EXP      (-23.083120654223414f)   // -16 * log2(e)
#define L2E        (1.4426950408889634f)
#define LN2        (0.6931471805599453f)
#define F_INF      (__int_as_float(0x7f800000))

__device__ float g_zs[T_LEN * KP];
__device__ float g_A [T_LEN * KP];
__device__ float g_rb[T_LEN][KP];
__device__ float g_pmax [T_LEN][GRID];  // per-CTA max of r_t (t>=1); plain stores, no reset
__device__ float g_pmax0[8];            // per-block max of r_0 from setup

__device__ __forceinline__ float ex2(float t) {
    float r; asm("ex2.approx.ftz.f32 %0,%1;" : "=f"(r) : "f"(t)); return r;
}
__device__ __forceinline__ float lg2(float t) {
    float r; asm("lg2.approx.f32 %0,%1;" : "=f"(r) : "f"(t)); return r;
}

// Setup: zs = mu + sigma*eps; A = -log(sp)-0.5log2pi-log_q; r0; per-block max(r0)
__global__ void __launch_bounds__(256) setup_kernel(const float* __restrict__ means,
                                                    const float* __restrict__ log_stds,
                                                    const float* __restrict__ eps) {
    __shared__ float red[8];
    int tid = threadIdx.x;
    int idx = blockIdx.x * 256 + tid;              // grid covers T_LEN*KP exactly
    int t = idx >> 11;
    int k = idx & (KP - 1);
    float mu = means[t];
    float sg = expf(log_stds[t]);
    float z  = fmaf(sg, eps[idx], mu);
    float zq = (z - mu) / sg;
    float lq = fmaf(-0.5f * zq, zq, -logf(sg)) - HALF_L2PI;
    g_zs[idx] = z;
    g_A[idx]  = -LOG_SP - HALF_L2PI - lq;
    if (blockIdx.x < 8) {                          // t == 0 blocks
        float zz = z * 5.656854249492380f;         // z / sp
        float r0 = fmaf(-0.5f * zz, zz, -LOG_SP) - HALF_L2PI - lq;
        g_rb[0][k] = r0;
        float m = r0;
        #pragma unroll
        for (int s = 16; s; s >>= 1)
            m = fmaxf(m, __shfl_xor_sync(0xffffffffu, m, s));
        if ((tid & 31) == 0) red[tid >> 5] = m;
        __syncthreads();
        if (tid < 8) {
            float v = red[tid];
            #pragma unroll
            for (int s = 4; s; s >>= 1)
                v = fmaxf(v, __shfl_xor_sync(0xffu, v, s, 8));
            if (tid == 0) g_pmax0[blockIdx.x] = v;
        }
    }
}

// One scan step with PDL. Critical path post-sync: r copy + pmax reduce + mainloop.
__global__ void __launch_bounds__(BLOCK) step_kernel(int t) {
    __shared__ __align__(16) float4 zc4[KP / 4];   // -z_{t-1}
    __shared__ __align__(16) float4 rc4[KP / 4];   // raw r_{t-1}
    __shared__ float xsh;
    __shared__ float cred[CPB];

    const int tid  = threadIdx.x;
    const int wid  = tid >> 5;
    const int lane = tid & 31;
    const int c    = tid >> 4;                 // column-in-block 0..15
    const int g    = tid & (GPC - 1);
    const int k    = blockIdx.x * CPB + c;

    cudaTriggerProgrammaticLaunchCompletion();     // successor may launch now

    // ---- pre-sync prologue: setup-owned data only (setup done before step 1 entry) ----
    const float4* __restrict__ z4 = reinterpret_cast<const float4*>(g_zs + (t - 1) * KP);
    #pragma unroll
    for (int i = 0; i < KP / (4 * BLOCK); i++) {
        int f = tid + i * BLOCK;
        float4 v = z4[f];
        zc4[f] = make_float4(-v.x, -v.y, -v.z, -v.w);
    }
    const float zk = g_zs[t * KP + k];
    const float ak = g_A [t * KP + k];

    cudaGridDependencySynchronize();               // wait for r_{t-1} (and pmax)

    // ---- post-sync: copy raw r (float4); warp 0 reduces producer maxes in parallel ----
    const float4* __restrict__ r4 = reinterpret_cast<const float4*>(g_rb[t - 1]);
    #pragma unroll
    for (int i = 0; i < KP / (4 * BLOCK); i++) {
        int f = tid + i * BLOCK;
        rc4[f] = r4[f];
    }
    if (wid == 0) {
        const float* __restrict__ pm = (t == 1) ? g_pmax0 : g_pmax[t - 1];
        const int cnt = (t == 1) ? 8 : GRID;
        float m = -F_INF;
        for (int i = lane; i < cnt; i += 32) m = fmaxf(m, pm[i]);
        #pragma unroll
        for (int s = 16; s; s >>= 1)
            m = fmaxf(m, __shfl_xor_sync(0xffffffffu, m, s));
        if (lane == 0) xsh = m;
    }
    __syncthreads();
    const float x   = xsh;
    const float nxl = -x * L2E;

    // ---- mainloop: S = sum_j 2^(C2*d^2 + (r_j - x)*log2e) ----
    float S0 = 0.0f, S1 = 0.0f;
    #pragma unroll 8
    for (int i = 0; i < KP / (4 * GPC); i++) {     // 32 iters, 4 pairs each
        int f = i * GPC + g;                       // same f across both half-warps -> LDS broadcast
        float4 zv = zc4[f];
        float4 rv = rc4[f];
        float d0 = zk + zv.x, d1 = zk + zv.y, d2 = zk + zv.z, d3 = zk + zv.w;
        float t0 = fmaf(C2EXP * d0, d0, fmaf(rv.x, L2E, nxl));
        float t1 = fmaf(C2EXP * d1, d1, fmaf(rv.y, L2E, nxl));
        float t2 = fmaf(C2EXP * d2, d2, fmaf(rv.z, L2E, nxl));
        float t3 = fmaf(C2EXP * d3, d3, fmaf(rv.w, L2E, nxl));
        S0 += ex2(t0);
        S1 += ex2(t1);
        S0 += ex2(t2);
        S1 += ex2(t3);
    }
    float S = S0 + S1;
    #pragma unroll
    for (int m = GPC / 2; m; m >>= 1)
        S += __shfl_xor_sync(0xffffffffu, S, m, GPC);

    // ---- epilogue: write r_out, publish per-CTA max ----
    if (g == 0) {
        float val = x + ak + lg2(fmaxf(S, 1e-37f)) * LN2 - LOG_K;
        g_rb[t][k] = val;
        cred[c] = val;
    }
    __syncthreads();
    if (tid < CPB) {
        float v = cred[tid];
        #pragma unroll
        for (int s = CPB / 2; s; s >>= 1)
            v = fmaxf(v, __shfl_xor_sync((1u << CPB) - 1u, v, s, CPB));
        if (tid == 0) g_pmax[t][blockIdx.x] = v;
    }
}

// Final: out = x + y + log(sum_j exp(r_j - x)*exp(L_j - y)) - logK
__global__ void __launch_bounds__(256) final_kernel(float* __restrict__ out) {
    __shared__ float sr[KP];
    __shared__ float sL[KP];
    __shared__ float red[16];
    const int tid  = threadIdx.x;
    const int wid  = tid >> 5;
    const int lane = tid & 31;

    cudaGridDependencySynchronize();

    const float* __restrict__ zrow = g_zs + (T_LEN - 1) * KP;
    const float* __restrict__ rin  = g_rb[T_LEN - 1];
    float lr = -F_INF, lL = -F_INF;
    #pragma unroll
    for (int i = 0; i < KP / 256; i++) {
        int j = tid + i * 256;
        float r  = rin[j];
        float dd = 0.5f - zrow[j];
        float Lv = fmaf(-0.5f * dd, dd, -HALF_L2PI);
        sr[j] = r; sL[j] = Lv;
        lr = fmaxf(lr, r);
        lL = fmaxf(lL, Lv);
    }
    #pragma unroll
    for (int m = 16; m; m >>= 1) {
        lr = fmaxf(lr, __shfl_xor_sync(0xffffffffu, lr, m));
        lL = fmaxf(lL, __shfl_xor_sync(0xffffffffu, lL, m));
    }
    if (lane == 0) { red[wid] = lr; red[8 + wid] = lL; }
    __syncthreads();
    float x = red[0], y = red[8];
    #pragma unroll
    for (int w = 1; w < 8; w++) {
        x = fmaxf(x, red[w]);
        y = fmaxf(y, red[8 + w]);
    }

    float S = 0.0f;
    #pragma unroll
    for (int i = 0; i < KP / 256; i++) {
        int j = tid + i * 256;
        S += ex2(((sr[j] - x) + (sL[j] - y)) * L2E);
    }
    #pragma unroll
    for (int m = 16; m; m >>= 1)
        S += __shfl_xor_sync(0xffffffffu, S, m);
    if (lane == 0) red[wid] = S;
    __syncthreads();
    if (tid == 0) {
        float tot = 0.0f;
        #pragma unroll
        for (int w = 0; w < 8; w++) tot += red[w];
        out[0] = x + y + logf(tot) - LOG_K;
    }
}

extern "C" void kernel_launch(void* const* d_in, const int* in_sizes, int n_in,
                              void* d_out, int out_size) {
    const float* means    = (const float*)d_in[0];
    const float* log_stds = (const float*)d_in[1];
    const float* eps      = (const float*)d_in[2];
    float* out = (float*)d_out;

    setup_kernel<<<(T_LEN * KP) / 256, 256>>>(means, log_stds, eps);

    cudaLaunchAttribute attr[1];
    attr[0].id = cudaLaunchAttributeProgrammaticStreamSerialization;
    attr[0].val.programmaticStreamSerializationAllowed = 1;

    cudaLaunchConfig_t cfg = {};
    cfg.gridDim  = dim3(GRID, 1, 1);
    cfg.blockDim = dim3(BLOCK, 1, 1);
    cfg.dynamicSmemBytes = 0;
    cfg.stream = 0;
    cfg.attrs = attr;
    cfg.numAttrs = 1;

    for (int t = 1; t < T_LEN; t++)
        cudaLaunchKernelEx(&cfg, step_kernel, t);

    cudaLaunchConfig_t cfgf = cfg;
    cfgf.gridDim  = dim3(1, 1, 1);
    cfgf.blockDim = dim3(256, 1, 1);
    cudaLaunchKernelEx(&cfgf, final_kernel, out);
}